// round 1
// baseline (speedup 1.0000x reference)
#include <cuda_runtime.h>

// Problem constants (fixed shapes per reference)
#define KROWS 1025
#define F     8192
#define NCHUNK 8
#define ROWS_PER_CHUNK 128   // (KROWS-1)/NCHUNK = 1024/8

// Device scratch (no allocations allowed in kernel_launch)
__device__ float g_partial[NCHUNK * F];
__device__ float g_scale[F];
__device__ float g_half[F];

// Kernel 1: partial column-wise sum of |x| over rows 1..1024, split into 8 chunks.
__global__ void relu_z_partial_abs(const float* __restrict__ x) {
    int f = blockIdx.x * blockDim.x + threadIdx.x;   // 0..F-1
    int chunk = blockIdx.y;                          // 0..7
    int r0 = 1 + chunk * ROWS_PER_CHUNK;
    int r1 = r0 + ROWS_PER_CHUNK;                    // <= 1025
    float s = 0.0f;
    const float* p = x + (size_t)r0 * F + f;
    #pragma unroll 8
    for (int r = r0; r < r1; ++r) {
        s += fabsf(*p);
        p += F;
    }
    g_partial[chunk * F + f] = s;
}

// Kernel 2: finalize abssum -> scale/half; write output row 0.
__global__ void relu_z_finalize(const float* __restrict__ x,
                                const float* __restrict__ lambdas,
                                float* __restrict__ out) {
    int f = blockIdx.x * blockDim.x + threadIdx.x;
    if (f >= F) return;
    float abssum = 0.0f;
    #pragma unroll
    for (int c = 0; c < NCHUNK; ++c) abssum += g_partial[c * F + f];

    float ctr = x[f];                 // x[0][f]
    float l = ctr - abssum;
    float u = ctr + abssum;
    float lam = lambdas[f];

    float pos   = (l > 0.0f) ? 1.0f : 0.0f;
    float cross = ((u > 0.0f) && (l < 0.0f)) ? 1.0f : 0.0f;
    float d     = fmaxf(-l * lam, u * (1.0f - lam));
    float scale = pos + cross * lam;
    float half  = 0.5f * cross * d;

    g_scale[f] = scale;
    g_half[f]  = half;
    out[f] = scale * ctr + half;      // center row
}

// Kernel 3: out[r] = scale * x[r] for r = 1..KROWS-1, float4 vectorized.
__global__ void relu_z_scale_rows(const float* __restrict__ x,
                                  float* __restrict__ out) {
    // (KROWS-1) * F/4 = 1024 * 2048 = 2,097,152 float4 elements
    int idx = blockIdx.x * blockDim.x + threadIdx.x;
    const int per_row = F / 4;        // 2048
    int r = 1 + idx / per_row;
    int c4 = idx % per_row;
    if (r >= KROWS) return;

    const float4* xs = (const float4*)(x + (size_t)r * F);
    float4 v = xs[c4];
    const float4* sc = (const float4*)g_scale;
    float4 s = sc[c4];
    float4 o;
    o.x = s.x * v.x;
    o.y = s.y * v.y;
    o.z = s.z * v.z;
    o.w = s.w * v.w;
    float4* os = (float4*)(out + (size_t)r * F);
    os[c4] = o;
}

// Kernel 4: diagonal of the extension block.
__global__ void relu_z_diag(float* __restrict__ out) {
    int f = blockIdx.x * blockDim.x + threadIdx.x;
    if (f >= F) return;
    out[(size_t)(KROWS + f) * F + f] = g_half[f];
}

extern "C" void kernel_launch(void* const* d_in, const int* in_sizes, int n_in,
                              void* d_out, int out_size) {
    const float* x       = (const float*)d_in[0];
    const float* lambdas = (const float*)d_in[1];
    float* out           = (float*)d_out;

    // 1) Partial abs-sums: 32 col-blocks x 8 row-chunks
    {
        dim3 grid(F / 256, NCHUNK);
        relu_z_partial_abs<<<grid, 256>>>(x);
    }

    // 2) Finalize scale/half + center row
    relu_z_finalize<<<F / 256, 256>>>(x, lambdas, out);

    // 3) Scaled body rows (vectorized)
    {
        int total = (KROWS - 1) * (F / 4);   // 2,097,152
        relu_z_scale_rows<<<(total + 255) / 256, 256>>>(x, out);
    }

    // 4) Zero the F x F extension block (256 MB) via memset node
    cudaMemsetAsync(out + (size_t)KROWS * F, 0, (size_t)F * F * sizeof(float), 0);

    // 5) Diagonal writes
    relu_z_diag<<<F / 256, 256>>>(out);
}